// round 2
// baseline (speedup 1.0000x reference)
#include <cuda_runtime.h>

#define NATOMS_V 100
#define DIM    200
#define NSTR   208   // normal smem row stride (floats)
#define DUPSTR 404   // duplicated smem row stride (floats, holds 2*DIM)
#define LHID   6
#define LOUT   3
#define LPRED  3
#define NADD   4
#define DPRED  204   // DIM + NADD
#define BMOL   256
#define NA     32
#define NTOT   8192

typedef unsigned long long ull;

__device__ __forceinline__ void ffma2(ull& d, ull a, ull b) {
    asm("fma.rn.f32x2 %0, %1, %2, %0;" : "+l"(d) : "l"(a), "l"(b));
}
__device__ __forceinline__ ull dup_f32(float v) {
    float2 t = make_float2(v, v);
    return *(ull*)&t;
}

struct SmemLayout {
    float  bufA[NA][DUPSTR];   // duplicated activations  (51,712 B)
    float  bufB[NA][NSTR];     // normal activations      (26,624 B)
    float2 msmd[NA][NA];       // duplicated message mat   (8,192 B)
    float  d2s[NA][NA];        // squared distances        (4,096 B)
    float  gam[LHID][NA];      //                            (768 B)
    float  pv[2][DPRED + 4];   // pred MLP ping-pong       (1,664 B)
    float  red[8];
    int    at[NA];
};   // ~93.2 KB -> 2 CTAs/SM

// C[i][c] = relu(bias[c] + sum_k A[i][k] * W[k][c])
// warp w: rows 4w..4w+3. lane: col pairs c = 2*lane + 64u (u=0..2), u=3: c=192+2*lane (lane<4)
template<bool SRC_DUP, bool DST_DUP>
__device__ __forceinline__ void gemm_relu(const float* __restrict__ src, int sstr,
                                          const float* __restrict__ W,
                                          const float* __restrict__ bias,
                                          float* __restrict__ dst, int dstr, int tid)
{
    const int w = tid >> 5, lane = tid & 31, i0 = w * 4;
    const bool has3 = (lane < 4);
    ull acc[4][4];
    #pragma unroll
    for (int r = 0; r < 4; r++)
        #pragma unroll
        for (int u = 0; u < 4; u++) acc[r][u] = 0ull;

    const float* s0 = src + i0 * sstr;

    #pragma unroll 2
    for (int k = 0; k < DIM; k++) {
        ull a[4];
        #pragma unroll
        for (int r = 0; r < 4; r++) {
            if (SRC_DUP) a[r] = *(const ull*)(s0 + r * sstr + 2 * k);   // LDS.64 broadcast, pre-dup
            else         a[r] = dup_f32(s0[r * sstr + k]);              // LDS.32 + dup
        }
        const float* Wk = W + k * DIM;
        ull w0 = *(const ull*)(Wk + 2 * lane);          // coalesced LDG.64
        ull w1 = *(const ull*)(Wk + 2 * lane + 64);
        ull w2 = *(const ull*)(Wk + 2 * lane + 128);
        #pragma unroll
        for (int r = 0; r < 4; r++) {
            ffma2(acc[r][0], a[r], w0);
            ffma2(acc[r][1], a[r], w1);
            ffma2(acc[r][2], a[r], w2);
        }
        if (has3) {
            ull w3 = *(const ull*)(Wk + 192 + 2 * lane);
            #pragma unroll
            for (int r = 0; r < 4; r++) ffma2(acc[r][3], a[r], w3);
        }
    }

    #pragma unroll
    for (int u = 0; u < 4; u++) {
        if (u == 3 && !has3) break;
        const int c = (u < 3) ? (2 * lane + 64 * u) : (192 + 2 * lane);
        const float2 bv = *(const float2*)(bias + c);
        #pragma unroll
        for (int r = 0; r < 4; r++) {
            float2 av = *(float2*)&acc[r][u];
            float x = fmaxf(av.x + bv.x, 0.f);
            float y = fmaxf(av.y + bv.y, 0.f);
            if (DST_DUP)
                *(float4*)(dst + (i0 + r) * dstr + 2 * c) = make_float4(x, x, y, y);
            else
                *(float2*)(dst + (i0 + r) * dstr + c) = make_float2(x, y);
        }
    }
}

// dst(dup) = normalize_row( hv + M @ hv ), hv normal layout, M pre-duplicated
__device__ __forceinline__ void mix_normalize(const float (*hv)[NSTR],
                                              const float2 (*msmd)[NA],
                                              float (*dstd)[DUPSTR], int tid)
{
    const int w = tid >> 5, lane = tid & 31, i0 = w * 4;
    const bool has3 = (lane < 4);
    const int c0 = 2 * lane, c3 = 192 + 2 * lane;

    ull acc[4][4];
    #pragma unroll
    for (int r = 0; r < 4; r++) {
        acc[r][0] = *(const ull*)&hv[i0 + r][c0];
        acc[r][1] = *(const ull*)&hv[i0 + r][c0 + 64];
        acc[r][2] = *(const ull*)&hv[i0 + r][c0 + 128];
        acc[r][3] = has3 ? *(const ull*)&hv[i0 + r][c3] : 0ull;
    }

    #pragma unroll 4
    for (int j = 0; j < NA; j++) {
        ull m[4];
        #pragma unroll
        for (int r = 0; r < 4; r++) m[r] = *(const ull*)&msmd[i0 + r][j];  // broadcast
        ull h0 = *(const ull*)&hv[j][c0];
        ull h1 = *(const ull*)&hv[j][c0 + 64];
        ull h2 = *(const ull*)&hv[j][c0 + 128];
        #pragma unroll
        for (int r = 0; r < 4; r++) {
            ffma2(acc[r][0], m[r], h0);
            ffma2(acc[r][1], m[r], h1);
            ffma2(acc[r][2], m[r], h2);
        }
        if (has3) {
            ull h3 = *(const ull*)&hv[j][c3];
            #pragma unroll
            for (int r = 0; r < 4; r++) ffma2(acc[r][3], m[r], h3);
        }
    }

    #pragma unroll
    for (int r = 0; r < 4; r++) {
        float ss = 0.f;
        #pragma unroll
        for (int u = 0; u < 4; u++) {
            float2 v = *(float2*)&acc[r][u];
            ss += v.x * v.x + v.y * v.y;
        }
        #pragma unroll
        for (int o = 16; o > 0; o >>= 1)
            ss += __shfl_xor_sync(0xffffffffu, ss, o);
        const float scale = 1.f / fmaxf(sqrtf(ss), 1e-12f);
        #pragma unroll
        for (int u = 0; u < 3; u++) {
            float2 v = *(float2*)&acc[r][u];
            const int c = c0 + 64 * u;
            *(float4*)&dstd[i0 + r][2 * c] =
                make_float4(v.x * scale, v.x * scale, v.y * scale, v.y * scale);
        }
        if (has3) {
            float2 v = *(float2*)&acc[r][3];
            *(float4*)&dstd[i0 + r][2 * c3] =
                make_float4(v.x * scale, v.x * scale, v.y * scale, v.y * scale);
        }
    }
}

__global__ __launch_bounds__(256, 2)
void mgnn_kernel(const int*   __restrict__ atoms,
                 const float* __restrict__ dist,
                 const float* __restrict__ adducts,
                 const float* __restrict__ embed_atom,
                 const float* __restrict__ gamma_tab,
                 const float* __restrict__ W_atom_w,
                 const float* __restrict__ W_atom_b,
                 const float* __restrict__ W_out_w,
                 const float* __restrict__ W_out_b,
                 const float* __restrict__ W_pred_w,
                 const float* __restrict__ W_pred_b,
                 const float* __restrict__ W_prop_w,
                 const float* __restrict__ W_prop_b,
                 float* __restrict__ out)
{
    extern __shared__ char smem_raw[];
    SmemLayout& sm = *reinterpret_cast<SmemLayout*>(smem_raw);

    const int m = blockIdx.x;
    const int tid = threadIdx.x;
    const int base = m * NA;

    // ---- setup ----
    if (tid < NA) sm.at[tid] = atoms[base + tid];
    __syncthreads();
    for (int idx = tid; idx < NA * DIM; idx += 256) {
        const int i = idx / DIM, k = idx - i * DIM;
        const float v = embed_atom[sm.at[i] * DIM + k];
        *(float2*)&sm.bufA[i][2 * k] = make_float2(v, v);   // duplicated
    }
    for (int idx = tid; idx < NA * NA; idx += 256) {
        const int i = idx >> 5, j = idx & 31;
        const float d = dist[(base + i) * NTOT + base + j];
        sm.d2s[i][j] = d * d;
    }
    for (int idx = tid; idx < LHID * NA; idx += 256) {
        const int l = idx >> 5, j = idx & 31;
        sm.gam[l][j] = gamma_tab[l * NATOMS_V + sm.at[j]];
    }
    __syncthreads();

    // ---- hidden layers ----
    for (int l = 0; l < LHID; l++) {
        gemm_relu<true, false>(&sm.bufA[0][0], DUPSTR,
                               W_atom_w + l * DIM * DIM, W_atom_b + l * DIM,
                               &sm.bufB[0][0], NSTR, tid);
        __syncthreads();
        for (int idx = tid; idx < NA * NA; idx += 256) {
            const int i = idx >> 5, j = idx & 31;
            const float e = __expf(-sm.gam[l][j] * sm.d2s[i][j]);
            sm.msmd[i][j] = make_float2(e, e);              // duplicated
        }
        __syncthreads();
        mix_normalize(sm.bufB, sm.msmd, sm.bufA, tid);
        __syncthreads();
    }

    // ---- output layers ----
    gemm_relu<true, false>(&sm.bufA[0][0], DUPSTR, W_out_w + 0 * DIM * DIM,
                           W_out_b + 0 * DIM, &sm.bufB[0][0], NSTR, tid);
    __syncthreads();
    gemm_relu<false, true>(&sm.bufB[0][0], NSTR, W_out_w + 1 * DIM * DIM,
                           W_out_b + 1 * DIM, &sm.bufA[0][0], DUPSTR, tid);
    __syncthreads();
    gemm_relu<true, false>(&sm.bufA[0][0], DUPSTR, W_out_w + 2 * DIM * DIM,
                           W_out_b + 2 * DIM, &sm.bufB[0][0], NSTR, tid);
    __syncthreads();

    // ---- per-molecule sum + adducts ----
    if (tid < DIM) {
        float s = 0.f;
        #pragma unroll 8
        for (int i = 0; i < NA; i++) s += sm.bufB[i][tid];
        sm.pv[0][tid] = s;
    } else if (tid < DPRED) {
        sm.pv[0][tid] = adducts[m * NADD + (tid - DIM)];
    }
    __syncthreads();

    // ---- prediction MLP ----
    int cur = 0;
    for (int l = 0; l < LPRED; l++) {
        if (tid < DPRED) {
            const float* Wp = W_pred_w + l * DPRED * DPRED;
            float acc = W_pred_b[l * DPRED + tid];
            #pragma unroll 4
            for (int k = 0; k < DPRED; k++)
                acc += sm.pv[cur][k] * Wp[k * DPRED + tid];
            sm.pv[cur ^ 1][tid] = fmaxf(acc, 0.f);
        }
        __syncthreads();
        cur ^= 1;
    }

    // ---- final scalar ----
    float part = (tid < DPRED) ? sm.pv[cur][tid] * W_prop_w[tid] : 0.f;
    #pragma unroll
    for (int o = 16; o > 0; o >>= 1)
        part += __shfl_xor_sync(0xffffffffu, part, o);
    if ((tid & 31) == 0) sm.red[tid >> 5] = part;
    __syncthreads();
    if (tid == 0) {
        float s = 0.f;
        #pragma unroll
        for (int w2 = 0; w2 < 8; w2++) s += sm.red[w2];
        out[m] = s + W_prop_b[0];
    }
}

extern "C" void kernel_launch(void* const* d_in, const int* in_sizes, int n_in,
                              void* d_out, int out_size)
{
    const int*   atoms      = (const int*)  d_in[0];
    const float* dist       = (const float*)d_in[1];
    const float* adducts    = (const float*)d_in[2];
    const float* embed_atom = (const float*)d_in[3];
    const float* gamma_tab  = (const float*)d_in[4];
    const float* W_atom_w   = (const float*)d_in[5];
    const float* W_atom_b   = (const float*)d_in[6];
    const float* W_out_w    = (const float*)d_in[7];
    const float* W_out_b    = (const float*)d_in[8];
    const float* W_pred_w   = (const float*)d_in[9];
    const float* W_pred_b   = (const float*)d_in[10];
    const float* W_prop_w   = (const float*)d_in[11];
    const float* W_prop_b   = (const float*)d_in[12];
    float* out = (float*)d_out;

    const int smem_bytes = (int)sizeof(SmemLayout);
    cudaFuncSetAttribute(mgnn_kernel,
                         cudaFuncAttributeMaxDynamicSharedMemorySize, smem_bytes);
    mgnn_kernel<<<BMOL, 256, smem_bytes>>>(
        atoms, dist, adducts, embed_atom, gamma_tab,
        W_atom_w, W_atom_b, W_out_w, W_out_b,
        W_pred_w, W_pred_b, W_prop_w, W_prop_b, out);
}

// round 3
// speedup vs baseline: 1.5948x; 1.5948x over previous
#include <cuda_runtime.h>

#define NATOMS_V 100
#define DIM    200
#define NSTR   208   // normal smem row stride (floats)
#define DUPSTR 404   // duplicated smem row stride (floats)
#define LHID   6
#define LPRED  3
#define NADD   4
#define DPRED  204
#define BMOL   256
#define NA     32
#define NTOT   8192
#define THREADS 512

typedef unsigned long long ull;

__device__ __forceinline__ void ffma2(ull& d, ull a, ull b) {
    asm("fma.rn.f32x2 %0, %1, %2, %0;" : "+l"(d) : "l"(a), "l"(b));
}
__device__ __forceinline__ ull dup_f32(float v) {
    float2 t = make_float2(v, v);
    return *(ull*)&t;
}

struct SmemLayout {
    float  bufA[NA][DUPSTR];    // duplicated activations (51.7 KB)
    float  bufB[NA][NSTR];      // normal activations     (26.6 KB)
    float2 msmd[NA][NA];        // duplicated message mat  (8.2 KB)
    float  d2s[NA][NA];
    float  gam[LHID][NA];
    float  ssred[NA][2];        // per-row sumsq partials (per col-half)
    float  pv[2][DPRED + 4];
    float  part[2][DPRED + 4];  // pred-MLP k-split partials
    float  red[16];
    int    at[NA];
};  // ~93.6 KB -> 2 CTAs/SM (187 KB)

// C[i][c] = relu(bias[c] + sum_k A[i][k] * W[k][c]),  C written NORMAL layout.
// 16 warps: h = w>>3 selects column half, wr = w&7 selects 4 rows.
// half 0: col pairs co0 = 2*lane, co1 = 2*lane+64     (cols 0..127)
// half 1: co0 = 2*lane+128 (128..191), co1 = 192+2*lane (lane<4 only)
template<bool SRC_DUP>
__device__ __forceinline__ void gemm_relu(const float* __restrict__ src,
                                          const float* __restrict__ W,
                                          const float* __restrict__ bias,
                                          float* __restrict__ dstN, int tid)
{
    const int w = tid >> 5, lane = tid & 31;
    const int h = w >> 3, wr = w & 7, i0 = wr * 4;
    const bool v1 = (h == 0) || (lane < 4);          // co1 valid?
    const int co0 = 2 * lane + (h ? 128 : 0);
    const int co1 = h ? (192 + 2 * lane) : (2 * lane + 64);

    ull acc0[4], acc1[4];
    #pragma unroll
    for (int r = 0; r < 4; r++) { acc0[r] = 0ull; acc1[r] = 0ull; }

    const int sstr = SRC_DUP ? DUPSTR : NSTR;
    const float* s0 = src + i0 * sstr;

    #pragma unroll 2
    for (int k = 0; k < DIM; k += 2) {
        ull a[4][2];
        #pragma unroll
        for (int r = 0; r < 4; r++) {
            if (SRC_DUP) {
                float4 v = *(const float4*)(s0 + r * sstr + 2 * k);  // (a,a,a',a')
                a[r][0] = *(ull*)&v.x;
                a[r][1] = *(ull*)&v.z;
            } else {
                float2 v = *(const float2*)(s0 + r * sstr + k);
                a[r][0] = dup_f32(v.x);
                a[r][1] = dup_f32(v.y);
            }
        }
        #pragma unroll
        for (int kk = 0; kk < 2; kk++) {
            const float* Wk = W + (k + kk) * DIM;
            ull w0 = *(const ull*)(Wk + co0);
            ull w1 = v1 ? *(const ull*)(Wk + co1) : 0ull;
            #pragma unroll
            for (int r = 0; r < 4; r++) {
                ffma2(acc0[r], a[r][kk], w0);
                ffma2(acc1[r], a[r][kk], w1);
            }
        }
    }

    const float2 b0 = *(const float2*)(bias + co0);
    #pragma unroll
    for (int r = 0; r < 4; r++) {
        float2 v = *(float2*)&acc0[r];
        *(float2*)(dstN + (i0 + r) * NSTR + co0) =
            make_float2(fmaxf(v.x + b0.x, 0.f), fmaxf(v.y + b0.y, 0.f));
    }
    if (v1) {
        const float2 b1 = *(const float2*)(bias + co1);
        #pragma unroll
        for (int r = 0; r < 4; r++) {
            float2 v = *(float2*)&acc1[r];
            *(float2*)(dstN + (i0 + r) * NSTR + co1) =
                make_float2(fmaxf(v.x + b1.x, 0.f), fmaxf(v.y + b1.y, 0.f));
        }
    }
}

// dstA(dup) = normalize_row( hv + M @ hv ); hv normal, M pre-duplicated.
__device__ __forceinline__ void mix_normalize(float (*hv)[NSTR],
                                              const float2 (*msmd)[NA],
                                              float (*dstd)[DUPSTR],
                                              float (*ssred)[2], int tid)
{
    const int w = tid >> 5, lane = tid & 31;
    const int h = w >> 3, wr = w & 7, i0 = wr * 4;
    const bool v1 = (h == 0) || (lane < 4);
    const int co0 = 2 * lane + (h ? 128 : 0);
    const int co1 = h ? (192 + 2 * lane) : (2 * lane + 64);

    ull acc0[4], acc1[4];
    #pragma unroll
    for (int r = 0; r < 4; r++) {
        acc0[r] = *(const ull*)&hv[i0 + r][co0];
        acc1[r] = v1 ? *(const ull*)&hv[i0 + r][co1] : 0ull;
    }

    #pragma unroll 4
    for (int j = 0; j < NA; j++) {
        ull m[4];
        #pragma unroll
        for (int r = 0; r < 4; r++) m[r] = *(const ull*)&msmd[i0 + r][j];
        ull h0 = *(const ull*)&hv[j][co0];
        ull h1 = v1 ? *(const ull*)&hv[j][co1] : 0ull;
        #pragma unroll
        for (int r = 0; r < 4; r++) {
            ffma2(acc0[r], m[r], h0);
            ffma2(acc1[r], m[r], h1);
        }
    }

    // per-row sumsq partial for this column half
    #pragma unroll
    for (int r = 0; r < 4; r++) {
        float2 a0 = *(float2*)&acc0[r];
        float2 a1 = *(float2*)&acc1[r];
        float ss = a0.x * a0.x + a0.y * a0.y + a1.x * a1.x + a1.y * a1.y;
        #pragma unroll
        for (int o = 16; o > 0; o >>= 1)
            ss += __shfl_xor_sync(0xffffffffu, ss, o);
        if (lane == 0) ssred[i0 + r][h] = ss;
    }
    __syncthreads();
    #pragma unroll
    for (int r = 0; r < 4; r++) {
        const float tot = ssred[i0 + r][0] + ssred[i0 + r][1];
        const float scale = 1.f / fmaxf(sqrtf(tot), 1e-12f);
        float2 a0 = *(float2*)&acc0[r];
        *(float4*)&dstd[i0 + r][2 * co0] =
            make_float4(a0.x * scale, a0.x * scale, a0.y * scale, a0.y * scale);
        if (v1) {
            float2 a1 = *(float2*)&acc1[r];
            *(float4*)&dstd[i0 + r][2 * co1] =
                make_float4(a1.x * scale, a1.x * scale, a1.y * scale, a1.y * scale);
        }
    }
}

__global__ __launch_bounds__(THREADS, 2)
void mgnn_kernel(const int*   __restrict__ atoms,
                 const float* __restrict__ dist,
                 const float* __restrict__ adducts,
                 const float* __restrict__ embed_atom,
                 const float* __restrict__ gamma_tab,
                 const float* __restrict__ W_atom_w,
                 const float* __restrict__ W_atom_b,
                 const float* __restrict__ W_out_w,
                 const float* __restrict__ W_out_b,
                 const float* __restrict__ W_pred_w,
                 const float* __restrict__ W_pred_b,
                 const float* __restrict__ W_prop_w,
                 const float* __restrict__ W_prop_b,
                 float* __restrict__ out)
{
    extern __shared__ char smem_raw[];
    SmemLayout& sm = *reinterpret_cast<SmemLayout*>(smem_raw);

    const int m = blockIdx.x;
    const int tid = threadIdx.x;
    const int base = m * NA;

    // ---- setup ----
    if (tid < NA) sm.at[tid] = atoms[base + tid];
    __syncthreads();
    for (int idx = tid; idx < NA * DIM; idx += THREADS) {
        const int i = idx / DIM, k = idx - i * DIM;
        const float v = embed_atom[sm.at[i] * DIM + k];
        *(float2*)&sm.bufA[i][2 * k] = make_float2(v, v);
    }
    for (int idx = tid; idx < NA * NA; idx += THREADS) {
        const int i = idx >> 5, j = idx & 31;
        const float d = dist[(base + i) * NTOT + base + j];
        sm.d2s[i][j] = d * d;
    }
    for (int idx = tid; idx < LHID * NA; idx += THREADS) {
        const int l = idx >> 5, j = idx & 31;
        sm.gam[l][j] = gamma_tab[l * NATOMS_V + sm.at[j]];
    }
    __syncthreads();

    // ---- hidden layers ----
    for (int l = 0; l < LHID; l++) {
        gemm_relu<true>(&sm.bufA[0][0], W_atom_w + l * DIM * DIM,
                        W_atom_b + l * DIM, &sm.bufB[0][0], tid);
        __syncthreads();
        for (int idx = tid; idx < NA * NA; idx += THREADS) {
            const int i = idx >> 5, j = idx & 31;
            const float e = __expf(-sm.gam[l][j] * sm.d2s[i][j]);
            sm.msmd[i][j] = make_float2(e, e);
        }
        __syncthreads();
        mix_normalize(sm.bufB, sm.msmd, sm.bufA, sm.ssred, tid);
        __syncthreads();
    }

    // ---- output layers ----
    gemm_relu<true>(&sm.bufA[0][0], W_out_w + 0 * DIM * DIM,
                    W_out_b + 0 * DIM, &sm.bufB[0][0], tid);
    __syncthreads();
    // layer 1: normal src bufB -> need dup dst for layer 2; write normal into
    // bufA's first NSTR columns? No: use non-dup src gemm into bufB is unsafe
    // (src==dst). Write into bufA region reinterpreted as normal buffer.
    gemm_relu<false>(&sm.bufB[0][0], W_out_w + 1 * DIM * DIM,
                     W_out_b + 1 * DIM, (float*)&sm.bufA[0][0], tid);  // normal layout, stride NSTR fits in bufA
    __syncthreads();
    gemm_relu<false>((float*)&sm.bufA[0][0], W_out_w + 2 * DIM * DIM,
                     W_out_b + 2 * DIM, &sm.bufB[0][0], tid);
    __syncthreads();

    // ---- per-molecule sum + adducts ----
    if (tid < DIM) {
        float s = 0.f;
        #pragma unroll 8
        for (int i = 0; i < NA; i++) s += sm.bufB[i][tid];
        sm.pv[0][tid] = s;
    } else if (tid < DPRED) {
        sm.pv[0][tid] = adducts[m * NADD + (tid - DIM)];
    }
    __syncthreads();

    // ---- prediction MLP: k split across two thread groups ----
    int cur = 0;
    for (int l = 0; l < LPRED; l++) {
        const int grp = tid >> 8;             // 0 or 1
        const int col = tid & 255;
        if (col < DPRED) {
            const float* Wp = W_pred_w + l * DPRED * DPRED;
            const int k0 = grp * 102, k1 = k0 + 102;
            float acc = 0.f;
            #pragma unroll 4
            for (int k = k0; k < k1; k++)
                acc += sm.pv[cur][k] * Wp[k * DPRED + col];
            sm.part[grp][col] = acc;
        }
        __syncthreads();
        if (tid < DPRED)
            sm.pv[cur ^ 1][tid] = fmaxf(sm.part[0][tid] + sm.part[1][tid]
                                        + W_pred_b[l * DPRED + tid], 0.f);
        __syncthreads();
        cur ^= 1;
    }

    // ---- final scalar ----
    float p = (tid < DPRED) ? sm.pv[cur][tid] * W_prop_w[tid] : 0.f;
    #pragma unroll
    for (int o = 16; o > 0; o >>= 1)
        p += __shfl_xor_sync(0xffffffffu, p, o);
    if ((tid & 31) == 0) sm.red[tid >> 5] = p;
    __syncthreads();
    if (tid == 0) {
        float s = 0.f;
        #pragma unroll
        for (int w2 = 0; w2 < 16; w2++) s += sm.red[w2];
        out[m] = s + W_prop_b[0];
    }
}

extern "C" void kernel_launch(void* const* d_in, const int* in_sizes, int n_in,
                              void* d_out, int out_size)
{
    const int*   atoms      = (const int*)  d_in[0];
    const float* dist       = (const float*)d_in[1];
    const float* adducts    = (const float*)d_in[2];
    const float* embed_atom = (const float*)d_in[3];
    const float* gamma_tab  = (const float*)d_in[4];
    const float* W_atom_w   = (const float*)d_in[5];
    const float* W_atom_b   = (const float*)d_in[6];
    const float* W_out_w    = (const float*)d_in[7];
    const float* W_out_b    = (const float*)d_in[8];
    const float* W_pred_w   = (const float*)d_in[9];
    const float* W_pred_b   = (const float*)d_in[10];
    const float* W_prop_w   = (const float*)d_in[11];
    const float* W_prop_b   = (const float*)d_in[12];
    float* out = (float*)d_out;

    const int smem_bytes = (int)sizeof(SmemLayout);
    cudaFuncSetAttribute(mgnn_kernel,
                         cudaFuncAttributeMaxDynamicSharedMemorySize, smem_bytes);
    mgnn_kernel<<<BMOL, THREADS, smem_bytes>>>(
        atoms, dist, adducts, embed_atom, gamma_tab,
        W_atom_w, W_atom_b, W_out_w, W_out_b,
        W_pred_w, W_pred_b, W_prop_w, W_prop_b, out);
}